// round 1
// baseline (speedup 1.0000x reference)
#include <cuda_runtime.h>
#include <math.h>

#define NROWS 8192   // B*Hs*Ws = 2*64*64
#define CDIM  256
#define HEADS 4
#define HD    64
#define GRIDW 64     // Hs = Ws

// -------- scratch (no allocations allowed) --------
__device__ float g_qkv[NROWS * 768];
__device__ float g_qr[NROWS * CDIM];
__device__ float g_kr[NROWS * CDIM];
__device__ float g_width[NROWS * HEADS];
__device__ float g_sharp[NROWS * HEADS];
__device__ float g_attn[NROWS * CDIM];
__device__ float g_irms[NROWS];
__device__ float g_merged[NROWS * CDIM];

__device__ __forceinline__ float sigm(float x) { return 1.f / (1.f + expf(-x)); }
__device__ __forceinline__ float silu(float x) { return x / (1.f + expf(-x)); }

// ============================================================================
// Generic fp32 SGEMM: 128x128 tile, BK=16, 256 threads, 8x8 per thread.
// MODE 0: C = silu(acc)
// MODE 1: gate-merge epilogue:
//   g = sigmoid(silu(acc + bias[n]))
//   C = g * A[m*lda+n] + (1-g) * attn[m*256+n]*irms[m]*won[n]
// Dims assumed multiples of tile sizes (true for this problem).
// ============================================================================
template <int MODE>
__global__ __launch_bounds__(256) void gemm_k(
    const float* __restrict__ A, int lda,
    const float* __restrict__ B, int ldb,
    float* __restrict__ Cp, int ldc,
    int K,
    const float* __restrict__ bias,
    const float* __restrict__ attn,
    const float* __restrict__ irms,
    const float* __restrict__ won)
{
    __shared__ float As[16][132];
    __shared__ float Bs[16][132];
    const int tid = threadIdx.x;
    const int m0 = blockIdx.y * 128;
    const int n0 = blockIdx.x * 128;
    const int ty = tid >> 4, tx = tid & 15;

    float acc[8][8];
#pragma unroll
    for (int i = 0; i < 8; i++)
#pragma unroll
        for (int j = 0; j < 8; j++) acc[i][j] = 0.f;

    for (int k0 = 0; k0 < K; k0 += 16) {
#pragma unroll
        for (int it = 0; it < 2; it++) {
            int lin = tid + it * 256;
            // A tile: 128 rows x 16 cols (store transposed)
            int r = lin >> 2, c4 = (lin & 3) << 2;
            float4 av = *(const float4*)&A[(size_t)(m0 + r) * lda + k0 + c4];
            As[c4 + 0][r] = av.x;
            As[c4 + 1][r] = av.y;
            As[c4 + 2][r] = av.z;
            As[c4 + 3][r] = av.w;
            // B tile: 16 rows x 128 cols
            int rb = lin >> 5, cb = (lin & 31) << 2;
            *(float4*)&Bs[rb][cb] = *(const float4*)&B[(size_t)(k0 + rb) * ldb + n0 + cb];
        }
        __syncthreads();
#pragma unroll
        for (int kk = 0; kk < 16; kk++) {
            float a[8], b[8];
            *(float4*)&a[0] = *(float4*)&As[kk][ty * 4];
            *(float4*)&a[4] = *(float4*)&As[kk][64 + ty * 4];
            *(float4*)&b[0] = *(float4*)&Bs[kk][tx * 4];
            *(float4*)&b[4] = *(float4*)&Bs[kk][64 + tx * 4];
#pragma unroll
            for (int i = 0; i < 8; i++)
#pragma unroll
                for (int j = 0; j < 8; j++) acc[i][j] += a[i] * b[j];
        }
        __syncthreads();
    }

#pragma unroll
    for (int i = 0; i < 8; i++) {
        int m = m0 + ((i < 4) ? (ty * 4 + i) : (64 + ty * 4 + i - 4));
#pragma unroll
        for (int j = 0; j < 8; j++) {
            int n = n0 + ((j < 4) ? (tx * 4 + j) : (64 + tx * 4 + j - 4));
            float val = acc[i][j];
            if (MODE == 0) {
                val = silu(val);
            } else {
                float gz = val + bias[n];
                gz = silu(gz);
                float g = sigm(gz);
                float vv = A[(size_t)m * lda + n];
                float o = attn[(size_t)m * 256 + n] * irms[m] * won[n];
                val = g * vv + (1.f - g) * o;
            }
            Cp[(size_t)m * ldc + n] = val;
        }
    }
}

// ============================================================================
// width/sharpness projection: warp per row, N=8 outputs.
// ============================================================================
__global__ __launch_bounds__(256) void wp_k(
    const float* __restrict__ x, const float* __restrict__ W,
    const float* __restrict__ bias,
    float* __restrict__ width, float* __restrict__ sharp)
{
    int row = (blockIdx.x * 256 + threadIdx.x) >> 5;
    int lane = threadIdx.x & 31;
    if (row >= NROWS) return;
    const float* xr = x + (size_t)row * 256;
    float acc[8] = {0, 0, 0, 0, 0, 0, 0, 0};
    for (int k = lane; k < 256; k += 32) {
        float xv = xr[k];
#pragma unroll
        for (int j = 0; j < 8; j++) acc[j] += xv * W[k * 8 + j];
    }
#pragma unroll
    for (int off = 16; off; off >>= 1)
#pragma unroll
        for (int j = 0; j < 8; j++) acc[j] += __shfl_xor_sync(0xffffffffu, acc[j], off);
    if (lane == 0) {
#pragma unroll
        for (int j = 0; j < 4; j++) {
            float wr = silu(acc[j] + bias[j]);
            width[row * 4 + j] = sigm(wr) * 4.2426406871192851f + 0.5f;
            float sr = silu(acc[4 + j] + bias[4 + j]);
            sharp[row * 4 + j] = sigm(sr) * 9.5f + 0.5f;
        }
    }
}

// ============================================================================
// rmsnorm + rope on q and k: warp per (row, head). rope positions index the
// HEAD axis (per reference), half = 32.
// ============================================================================
__global__ __launch_bounds__(256) void normrope_k(
    const float* __restrict__ qkv,
    const float* __restrict__ wq, const float* __restrict__ wk,
    float* __restrict__ qr, float* __restrict__ kr)
{
    int g = (blockIdx.x * 256 + threadIdx.x) >> 5;
    int lane = threadIdx.x & 31;
    if (g >= NROWS * HEADS) return;
    int row = g >> 2, h = g & 3;
    const float* qp = qkv + (size_t)row * 768 + h * 64;
    float q1 = qp[lane], q2 = qp[lane + 32];
    float k1 = qp[256 + lane], k2 = qp[256 + lane + 32];
    float sq = q1 * q1 + q2 * q2;
    float sk = k1 * k1 + k2 * k2;
#pragma unroll
    for (int off = 16; off; off >>= 1) {
        sq += __shfl_xor_sync(0xffffffffu, sq, off);
        sk += __shfl_xor_sync(0xffffffffu, sk, off);
    }
    float qi = rsqrtf(sq * (1.f / 64.f) + 1e-6f);
    float ki = rsqrtf(sk * (1.f / 64.f) + 1e-6f);
    q1 *= qi * wq[lane];
    q2 *= qi * wq[lane + 32];
    k1 *= ki * wk[lane];
    k2 *= ki * wk[lane + 32];
    // freq = 10000^(-lane/32); ln(10000) = 9.210340371976184
    float freq = expf(-9.210340371976184f * (float)lane * (1.f / 32.f));
    float ang = (float)h * freq;
    float cs = cosf(ang), sn = sinf(ang);
    size_t o = (size_t)row * 256 + h * 64;
    qr[o + lane] = q1 * cs - q2 * sn;
    qr[o + lane + 32] = q1 * sn + q2 * cs;
    kr[o + lane] = k1 * cs - k2 * sn;
    kr[o + lane + 32] = k1 * sn + k2 * cs;
}

// ============================================================================
// Local attention. Block = (8x8 spatial tile, head, batch). 256 threads.
// K/V halo tiles (14x14x64) in smem; 4 lanes cooperate per position
// (each owns 16 of 64 dims); scores staged in smem for softmax/AV.
// ============================================================================
__global__ __launch_bounds__(256) void attn_k(
    const float* __restrict__ qr, const float* __restrict__ kr,
    const float* __restrict__ qkv,  // v = cols [512,768)
    const float* __restrict__ width, const float* __restrict__ sharp,
    float* __restrict__ out)
{
    extern __shared__ float sm[];
    float* ks = sm;             // 14*14*64 = 12544
    float* vs = sm + 12544;     // 12544
    float* sc = sm + 25088;     // 64*52
    const int tile = blockIdx.x, h = blockIdx.y, b = blockIdx.z;
    const int ty0 = (tile >> 3) << 3;
    const int tx0 = (tile & 7) << 3;
    const int tid = threadIdx.x;

    for (int idx = tid; idx < 196 * 16; idx += 256) {
        int sp = idx >> 4, f = idx & 15;
        int yy = ty0 - 3 + sp / 14;
        int xx = tx0 - 3 + sp % 14;
        float4 kv = make_float4(0.f, 0.f, 0.f, 0.f);
        float4 vv = make_float4(0.f, 0.f, 0.f, 0.f);
        if (yy >= 0 && yy < GRIDW && xx >= 0 && xx < GRIDW) {
            int r = (b * GRIDW + yy) * GRIDW + xx;
            kv = *(const float4*)&kr[(size_t)r * 256 + h * 64 + f * 4];
            vv = *(const float4*)&qkv[(size_t)r * 768 + 512 + h * 64 + f * 4];
        }
        *(float4*)&ks[sp * 64 + f * 4] = kv;
        *(float4*)&vs[sp * 64 + f * 4] = vv;
    }
    __syncthreads();

    const int p = tid >> 2, sub = tid & 3;
    const int py = p >> 3, px = p & 7;
    const int row = (b * GRIDW + ty0 + py) * GRIDW + tx0 + px;

    float q[16];
#pragma unroll
    for (int i = 0; i < 4; i++)
        *(float4*)&q[i * 4] = *(const float4*)&qr[(size_t)row * 256 + h * 64 + sub * 16 + i * 4];
    const float wd = width[row * 4 + h];
    const float sh = sharp[row * 4 + h];

    for (int w = 0; w < 49; w++) {
        int wy = w / 7, wx = w % 7;
        const float* kp = &ks[((py + wy) * 14 + px + wx) * 64 + sub * 16];
        float s = 0.f;
#pragma unroll
        for (int i = 0; i < 16; i++) s += q[i] * kp[i];
        s += __shfl_xor_sync(0xffffffffu, s, 1);
        s += __shfl_xor_sync(0xffffffffu, s, 2);
        if (sub == 0) {
            float dy = (float)(wy - 3), dx = (float)(wx - 3);
            float rd = sqrtf(dy * dy + dx * dx);
            float soft = sigm((wd - rd) * sh);
            sc[p * 52 + w] = s * 0.125f - (1.f - soft) * 10000.f;
        }
    }
    __syncwarp();

    float mx = -1e30f;
    for (int w = sub; w < 49; w += 4) mx = fmaxf(mx, sc[p * 52 + w]);
    mx = fmaxf(mx, __shfl_xor_sync(0xffffffffu, mx, 1));
    mx = fmaxf(mx, __shfl_xor_sync(0xffffffffu, mx, 2));
    float sum = 0.f;
    for (int w = sub; w < 49; w += 4) {
        float e = expf(sc[p * 52 + w] - mx);
        sc[p * 52 + w] = e;
        sum += e;
    }
    sum += __shfl_xor_sync(0xffffffffu, sum, 1);
    sum += __shfl_xor_sync(0xffffffffu, sum, 2);
    __syncwarp();
    float inv = 1.f / sum;

    float o[16];
#pragma unroll
    for (int i = 0; i < 16; i++) o[i] = 0.f;
    for (int w = 0; w < 49; w++) {
        float a = sc[p * 52 + w];
        const float* vp = &vs[((py + w / 7) * 14 + px + w % 7) * 64 + sub * 16];
#pragma unroll
        for (int i = 0; i < 16; i++) o[i] += a * vp[i];
    }
#pragma unroll
    for (int i = 0; i < 4; i++) {
        float4 r = make_float4(o[i * 4] * inv, o[i * 4 + 1] * inv, o[i * 4 + 2] * inv, o[i * 4 + 3] * inv);
        *(float4*)&out[(size_t)row * 256 + h * 64 + sub * 16 + i * 4] = r;
    }
}

// ============================================================================
// inv-RMS per row of attention output.
// ============================================================================
__global__ __launch_bounds__(256) void irms_k(
    const float* __restrict__ attn, float* __restrict__ irms)
{
    int row = (blockIdx.x * 256 + threadIdx.x) >> 5;
    int lane = threadIdx.x & 31;
    if (row >= NROWS) return;
    const float* a = attn + (size_t)row * 256;
    float s = 0.f;
    for (int k = lane; k < 256; k += 32) {
        float v = a[k];
        s += v * v;
    }
#pragma unroll
    for (int off = 16; off; off >>= 1) s += __shfl_xor_sync(0xffffffffu, s, off);
    if (lane == 0) irms[row] = rsqrtf(s * (1.f / 256.f) + 1e-6f);
}

// ============================================================================
extern "C" void kernel_launch(void* const* d_in, const int* in_sizes, int n_in,
                              void* d_out, int out_size)
{
    const float* x      = (const float*)d_in[0];
    const float* W_qkv  = (const float*)d_in[1];
    const float* w_qn   = (const float*)d_in[2];
    const float* w_kn   = (const float*)d_in[3];
    const float* W_wp   = (const float*)d_in[4];
    const float* b_wp   = (const float*)d_in[5];
    const float* w_on   = (const float*)d_in[6];
    const float* W_out  = (const float*)d_in[7];
    const float* W_gate = (const float*)d_in[8];
    const float* b_gate = (const float*)d_in[9];
    float* out = (float*)d_out;

    float *qkv, *qr, *kr, *wd, *sh, *attn, *irms, *merged;
    cudaGetSymbolAddress((void**)&qkv, g_qkv);
    cudaGetSymbolAddress((void**)&qr, g_qr);
    cudaGetSymbolAddress((void**)&kr, g_kr);
    cudaGetSymbolAddress((void**)&wd, g_width);
    cudaGetSymbolAddress((void**)&sh, g_sharp);
    cudaGetSymbolAddress((void**)&attn, g_attn);
    cudaGetSymbolAddress((void**)&irms, g_irms);
    cudaGetSymbolAddress((void**)&merged, g_merged);

    const int SMEM_ATTN = (12544 * 2 + 64 * 52) * 4;  // 113664 B
    cudaFuncSetAttribute(attn_k, cudaFuncAttributeMaxDynamicSharedMemorySize, SMEM_ATTN);

    // 1) qkv = silu(x @ W_qkv)   [8192 x 768 x 256]
    gemm_k<0><<<dim3(6, 64), 256>>>(x, 256, W_qkv, 768, qkv, 768, 256,
                                    nullptr, nullptr, nullptr, nullptr);
    // 2) width/sharpness
    wp_k<<<NROWS / 8, 256>>>(x, W_wp, b_wp, wd, sh);
    // 3) rmsnorm + rope on q,k
    normrope_k<<<NROWS * HEADS / 8, 256>>>(qkv, w_qn, w_kn, qr, kr);
    // 4) local attention
    attn_k<<<dim3(64, HEADS, 2), 256, SMEM_ATTN>>>(qr, kr, qkv, wd, sh, attn);
    // 5) inv-rms of attention output
    irms_k<<<NROWS / 8, 256>>>(attn, irms);
    // 6) merged = gate*v + (1-gate)*rmsnorm(attn)   [8192 x 256 x 256]
    gemm_k<1><<<dim3(2, 64), 256>>>(qkv + 512, 768, W_gate, 256, merged, 256, 256,
                                    b_gate, attn, irms, w_on);
    // 7) out = silu(merged @ W_out)                 [8192 x 256 x 256]
    gemm_k<0><<<dim3(2, 64), 256>>>(merged, 256, W_out, 256, out, 256, 256,
                                    nullptr, nullptr, nullptr, nullptr);
}

// round 3
// speedup vs baseline: 1.0067x; 1.0067x over previous
#include <cuda_runtime.h>
#include <math.h>

#define NROWS 8192   // B*Hs*Ws = 2*64*64
#define CDIM  256
#define HEADS 4
#define HD    64
#define GRIDW 64     // Hs = Ws

// -------- scratch (no allocations allowed) --------
__device__ float g_qkv[NROWS * 768];
__device__ float g_qr[NROWS * CDIM];
__device__ float g_kr[NROWS * CDIM];
__device__ float g_width[NROWS * HEADS];
__device__ float g_sharp[NROWS * HEADS];
__device__ float g_attn[NROWS * CDIM];
__device__ float g_irms[NROWS];
__device__ float g_merged[NROWS * CDIM];

__device__ __forceinline__ float sigm(float x) { return 1.f / (1.f + expf(-x)); }
__device__ __forceinline__ float silu(float x) { return x / (1.f + expf(-x)); }

// ============================================================================
// Generic fp32 SGEMM: 128x128 tile, BK=16, 256 threads, 8x8 per thread.
// MODE 0: C = silu(acc)
// MODE 1: gate-merge epilogue:
//   g = sigmoid(silu(acc + bias[n]))
//   C = g * A[m*lda+n] + (1-g) * attn[m*256+n]*irms[m]*won[n]
// ============================================================================
template <int MODE>
__global__ __launch_bounds__(256) void gemm_k(
    const float* __restrict__ A, int lda,
    const float* __restrict__ B, int ldb,
    float* __restrict__ Cp, int ldc,
    int K,
    const float* __restrict__ bias,
    const float* __restrict__ attn,
    const float* __restrict__ irms,
    const float* __restrict__ won)
{
    __shared__ float As[16][132];
    __shared__ float Bs[16][132];
    const int tid = threadIdx.x;
    const int m0 = blockIdx.y * 128;
    const int n0 = blockIdx.x * 128;
    const int ty = tid >> 4, tx = tid & 15;

    float acc[8][8];
#pragma unroll
    for (int i = 0; i < 8; i++)
#pragma unroll
        for (int j = 0; j < 8; j++) acc[i][j] = 0.f;

    for (int k0 = 0; k0 < K; k0 += 16) {
#pragma unroll
        for (int it = 0; it < 2; it++) {
            int lin = tid + it * 256;
            int r = lin >> 2, c4 = (lin & 3) << 2;
            float4 av = *(const float4*)&A[(size_t)(m0 + r) * lda + k0 + c4];
            As[c4 + 0][r] = av.x;
            As[c4 + 1][r] = av.y;
            As[c4 + 2][r] = av.z;
            As[c4 + 3][r] = av.w;
            int rb = lin >> 5, cb = (lin & 31) << 2;
            *(float4*)&Bs[rb][cb] = *(const float4*)&B[(size_t)(k0 + rb) * ldb + n0 + cb];
        }
        __syncthreads();
#pragma unroll
        for (int kk = 0; kk < 16; kk++) {
            float a[8], b[8];
            *(float4*)&a[0] = *(float4*)&As[kk][ty * 4];
            *(float4*)&a[4] = *(float4*)&As[kk][64 + ty * 4];
            *(float4*)&b[0] = *(float4*)&Bs[kk][tx * 4];
            *(float4*)&b[4] = *(float4*)&Bs[kk][64 + tx * 4];
#pragma unroll
            for (int i = 0; i < 8; i++)
#pragma unroll
                for (int j = 0; j < 8; j++) acc[i][j] += a[i] * b[j];
        }
        __syncthreads();
    }

#pragma unroll
    for (int i = 0; i < 8; i++) {
        int m = m0 + ((i < 4) ? (ty * 4 + i) : (64 + ty * 4 + i - 4));
#pragma unroll
        for (int j = 0; j < 8; j++) {
            int n = n0 + ((j < 4) ? (tx * 4 + j) : (64 + tx * 4 + j - 4));
            float val = acc[i][j];
            if (MODE == 0) {
                val = silu(val);
            } else {
                float gz = val + bias[n];
                gz = silu(gz);
                float g = sigm(gz);
                float vv = A[(size_t)m * lda + n];
                float o = attn[(size_t)m * 256 + n] * irms[m] * won[n];
                val = g * vv + (1.f - g) * o;
            }
            Cp[(size_t)m * ldc + n] = val;
        }
    }
}

// ============================================================================
// width/sharpness projection: warp per row, N=8 outputs.
// ============================================================================
__global__ __launch_bounds__(256) void wp_k(
    const float* __restrict__ x, const float* __restrict__ W,
    const float* __restrict__ bias,
    float* __restrict__ width, float* __restrict__ sharp)
{
    int row = (blockIdx.x * 256 + threadIdx.x) >> 5;
    int lane = threadIdx.x & 31;
    if (row >= NROWS) return;
    const float* xr = x + (size_t)row * 256;
    float acc[8] = {0, 0, 0, 0, 0, 0, 0, 0};
    for (int k = lane; k < 256; k += 32) {
        float xv = xr[k];
#pragma unroll
        for (int j = 0; j < 8; j++) acc[j] += xv * W[k * 8 + j];
    }
#pragma unroll
    for (int off = 16; off; off >>= 1)
#pragma unroll
        for (int j = 0; j < 8; j++) acc[j] += __shfl_xor_sync(0xffffffffu, acc[j], off);
    if (lane == 0) {
#pragma unroll
        for (int j = 0; j < 4; j++) {
            float wr = silu(acc[j] + bias[j]);
            width[row * 4 + j] = sigm(wr) * 4.2426406871192851f + 0.5f;
            float sr = silu(acc[4 + j] + bias[4 + j]);
            sharp[row * 4 + j] = sigm(sr) * 9.5f + 0.5f;
        }
    }
}

// ============================================================================
// rmsnorm + rope on q and k: warp per (row, head). rope positions index the
// HEAD axis (per reference), half = 32.
// ============================================================================
__global__ __launch_bounds__(256) void normrope_k(
    const float* __restrict__ qkv,
    const float* __restrict__ wq, const float* __restrict__ wk,
    float* __restrict__ qr, float* __restrict__ kr)
{
    int g = (blockIdx.x * 256 + threadIdx.x) >> 5;
    int lane = threadIdx.x & 31;
    if (g >= NROWS * HEADS) return;
    int row = g >> 2, h = g & 3;
    const float* qp = qkv + (size_t)row * 768 + h * 64;
    float q1 = qp[lane], q2 = qp[lane + 32];
    float k1 = qp[256 + lane], k2 = qp[256 + lane + 32];
    float sq = q1 * q1 + q2 * q2;
    float sk = k1 * k1 + k2 * k2;
#pragma unroll
    for (int off = 16; off; off >>= 1) {
        sq += __shfl_xor_sync(0xffffffffu, sq, off);
        sk += __shfl_xor_sync(0xffffffffu, sk, off);
    }
    float qi = rsqrtf(sq * (1.f / 64.f) + 1e-6f);
    float ki = rsqrtf(sk * (1.f / 64.f) + 1e-6f);
    q1 *= qi * wq[lane];
    q2 *= qi * wq[lane + 32];
    k1 *= ki * wk[lane];
    k2 *= ki * wk[lane + 32];
    float freq = expf(-9.210340371976184f * (float)lane * (1.f / 32.f));
    float ang = (float)h * freq;
    float cs = cosf(ang), sn = sinf(ang);
    size_t o = (size_t)row * 256 + h * 64;
    qr[o + lane] = q1 * cs - q2 * sn;
    qr[o + lane + 32] = q1 * sn + q2 * cs;
    kr[o + lane] = k1 * cs - k2 * sn;
    kr[o + lane + 32] = k1 * sn + k2 * cs;
}

// ============================================================================
// Local attention, restructured for ILP.
// Block = (8x8 spatial tile, head, batch). 256 threads, 2 CTAs/SM.
// QK phase: thread = (position p, window-subset sub): full 64-dim q in
// registers, computes complete dot products for windows {sub, sub+4, ...}.
// 13 independent accumulator chains, ZERO shuffles.
// AV phase: thread = (position p, 16-dim chunk sub), 16 independent accs.
// ============================================================================
__global__ __launch_bounds__(256, 2) void attn_k(
    const float* __restrict__ qr, const float* __restrict__ kr,
    const float* __restrict__ qkv,  // v = cols [512,768)
    const float* __restrict__ width, const float* __restrict__ sharp,
    float* __restrict__ out)
{
    extern __shared__ float sm[];
    float* ks = sm;             // 14*14*64 = 12544
    float* vs = sm + 12544;     // 12544
    float* sc = sm + 25088;     // 64*52
    const int tile = blockIdx.x, h = blockIdx.y, b = blockIdx.z;
    const int ty0 = (tile >> 3) << 3;
    const int tx0 = (tile & 7) << 3;
    const int tid = threadIdx.x;

    // stage K/V halo (14x14x64 each)
    for (int idx = tid; idx < 196 * 16; idx += 256) {
        int sp = idx >> 4, f = idx & 15;
        int yy = ty0 - 3 + sp / 14;
        int xx = tx0 - 3 + sp % 14;
        float4 kv = make_float4(0.f, 0.f, 0.f, 0.f);
        float4 vv = make_float4(0.f, 0.f, 0.f, 0.f);
        if (yy >= 0 && yy < GRIDW && xx >= 0 && xx < GRIDW) {
            int r = (b * GRIDW + yy) * GRIDW + xx;
            kv = *(const float4*)&kr[(size_t)r * 256 + h * 64 + f * 4];
            vv = *(const float4*)&qkv[(size_t)r * 768 + 512 + h * 64 + f * 4];
        }
        *(float4*)&ks[sp * 64 + f * 4] = kv;
        *(float4*)&vs[sp * 64 + f * 4] = vv;
    }
    __syncthreads();

    const int p = tid >> 2, sub = tid & 3;
    const int py = p >> 3, px = p & 7;
    const int row = (b * GRIDW + ty0 + py) * GRIDW + tx0 + px;

    const float wd = width[row * 4 + h];
    const float sh = sharp[row * 4 + h];

    // ---- QK phase: full q in registers, disjoint windows per lane ----
    {
        float q[64];
#pragma unroll
        for (int i = 0; i < 16; i++)
            *(float4*)&q[i * 4] = *(const float4*)&qr[(size_t)row * 256 + h * 64 + i * 4];

#pragma unroll
        for (int j = 0; j < 13; j++) {
            int w = sub + 4 * j;
            if (w < 49) {
                int wy = w / 7, wx = w % 7;
                const float* kp = &ks[((py + wy) * 14 + px + wx) * 64];
                float s0 = 0.f, s1 = 0.f, s2 = 0.f, s3 = 0.f;
#pragma unroll
                for (int i = 0; i < 16; i++) {
                    float4 kv = *(const float4*)&kp[i * 4];
                    s0 += q[i * 4 + 0] * kv.x;
                    s1 += q[i * 4 + 1] * kv.y;
                    s2 += q[i * 4 + 2] * kv.z;
                    s3 += q[i * 4 + 3] * kv.w;
                }
                float s = (s0 + s1) + (s2 + s3);
                float dy = (float)(wy - 3), dx = (float)(wx - 3);
                float rd = sqrtf(dy * dy + dx * dx);
                float soft = sigm((wd - rd) * sh);
                sc[p * 52 + w] = s * 0.125f - (1.f - soft) * 10000.f;
            }
        }
    }
    __syncwarp();   // p's 4 lanes are in the same warp; scores visible

    // ---- softmax over 49 (4 lanes cooperate) ----
    float mx = -1e30f;
    for (int w = sub; w < 49; w += 4) mx = fmaxf(mx, sc[p * 52 + w]);
    mx = fmaxf(mx, __shfl_xor_sync(0xffffffffu, mx, 1));
    mx = fmaxf(mx, __shfl_xor_sync(0xffffffffu, mx, 2));
    float sum = 0.f;
    for (int w = sub; w < 49; w += 4) {
        float e = expf(sc[p * 52 + w] - mx);
        sc[p * 52 + w] = e;
        sum += e;
    }
    sum += __shfl_xor_sync(0xffffffffu, sum, 1);
    sum += __shfl_xor_sync(0xffffffffu, sum, 2);
    __syncwarp();
    float inv = 1.f / sum;

    // ---- AV phase: thread owns (p, 16 dims) ----
    float o[16];
#pragma unroll
    for (int i = 0; i < 16; i++) o[i] = 0.f;
    for (int w = 0; w < 49; w++) {
        float a = sc[p * 52 + w];
        const float* vp = &vs[((py + w / 7) * 14 + px + w % 7) * 64 + sub * 16];
#pragma unroll
        for (int i = 0; i < 16; i++) o[i] += a * vp[i];
    }
#pragma unroll
    for (int i = 0; i < 4; i++) {
        float4 r = make_float4(o[i * 4] * inv, o[i * 4 + 1] * inv, o[i * 4 + 2] * inv, o[i * 4 + 3] * inv);
        *(float4*)&out[(size_t)row * 256 + h * 64 + sub * 16 + i * 4] = r;
    }
}

// ============================================================================
// inv-RMS per row of attention output.
// ============================================================================
__global__ __launch_bounds__(256) void irms_k(
    const float* __restrict__ attn, float* __restrict__ irms)
{
    int row = (blockIdx.x * 256 + threadIdx.x) >> 5;
    int lane = threadIdx.x & 31;
    if (row >= NROWS) return;
    const float* a = attn + (size_t)row * 256;
    float s = 0.f;
    for (int k = lane; k < 256; k += 32) {
        float v = a[k];
        s += v * v;
    }
#pragma unroll
    for (int off = 16; off; off >>= 1) s += __shfl_xor_sync(0xffffffffu, s, off);
    if (lane == 0) irms[row] = rsqrtf(s * (1.f / 256.f) + 1e-6f);
}

// ============================================================================
extern "C" void kernel_launch(void* const* d_in, const int* in_sizes, int n_in,
                              void* d_out, int out_size)
{
    const float* x      = (const float*)d_in[0];
    const float* W_qkv  = (const float*)d_in[1];
    const float* w_qn   = (const float*)d_in[2];
    const float* w_kn   = (const float*)d_in[3];
    const float* W_wp   = (const float*)d_in[4];
    const float* b_wp   = (const float*)d_in[5];
    const float* w_on   = (const float*)d_in[6];
    const float* W_out  = (const float*)d_in[7];
    const float* W_gate = (const float*)d_in[8];
    const float* b_gate = (const float*)d_in[9];
    float* out = (float*)d_out;

    float *qkv, *qr, *kr, *wd, *sh, *attn, *irms, *merged;
    cudaGetSymbolAddress((void**)&qkv, g_qkv);
    cudaGetSymbolAddress((void**)&qr, g_qr);
    cudaGetSymbolAddress((void**)&kr, g_kr);
    cudaGetSymbolAddress((void**)&wd, g_width);
    cudaGetSymbolAddress((void**)&sh, g_sharp);
    cudaGetSymbolAddress((void**)&attn, g_attn);
    cudaGetSymbolAddress((void**)&irms, g_irms);
    cudaGetSymbolAddress((void**)&merged, g_merged);

    const int SMEM_ATTN = (12544 * 2 + 64 * 52) * 4;  // 113664 B
    cudaFuncSetAttribute(attn_k, cudaFuncAttributeMaxDynamicSharedMemorySize, SMEM_ATTN);

    // 1) qkv = silu(x @ W_qkv)   [8192 x 768 x 256]
    gemm_k<0><<<dim3(6, 64), 256>>>(x, 256, W_qkv, 768, qkv, 768, 256,
                                    nullptr, nullptr, nullptr, nullptr);
    // 2) width/sharpness
    wp_k<<<NROWS / 8, 256>>>(x, W_wp, b_wp, wd, sh);
    // 3) rmsnorm + rope on q,k
    normrope_k<<<NROWS * HEADS / 8, 256>>>(qkv, w_qn, w_kn, qr, kr);
    // 4) local attention
    attn_k<<<dim3(64, HEADS, 2), 256, SMEM_ATTN>>>(qr, kr, qkv, wd, sh, attn);
    // 5) inv-rms of attention output
    irms_k<<<NROWS / 8, 256>>>(attn, irms);
    // 6) merged = gate*v + (1-gate)*rmsnorm(attn)   [8192 x 256 x 256]
    gemm_k<1><<<dim3(2, 64), 256>>>(qkv + 512, 768, W_gate, 256, merged, 256, 256,
                                    b_gate, attn, irms, w_on);
    // 7) out = silu(merged @ W_out)                 [8192 x 256 x 256]
    gemm_k<0><<<dim3(2, 64), 256>>>(merged, 256, W_out, 256, out, 256, 256,
                                    nullptr, nullptr, nullptr, nullptr);
}

// round 4
// speedup vs baseline: 1.2061x; 1.1980x over previous
#include <cuda_runtime.h>
#include <math.h>

#define NROWS 8192   // B*Hs*Ws = 2*64*64
#define CDIM  256
#define HEADS 4
#define HD    64
#define GRIDW 64     // Hs = Ws
#define KST   68     // padded smem row stride (floats): 68%32=4 -> staggered banks

// -------- scratch (no allocations allowed) --------
__device__ float g_qkv[NROWS * 768];
__device__ float g_qr[NROWS * CDIM];
__device__ float g_kr[NROWS * CDIM];
__device__ float g_width[NROWS * HEADS];
__device__ float g_sharp[NROWS * HEADS];
__device__ float g_attn[NROWS * CDIM];
__device__ float g_irms[NROWS];
__device__ float g_merged[NROWS * CDIM];

__device__ __forceinline__ float sigm(float x) { return 1.f / (1.f + expf(-x)); }
__device__ __forceinline__ float silu(float x) { return x / (1.f + expf(-x)); }

// ============================================================================
// Generic fp32 SGEMM: 128x128 tile, BK=16, 256 threads, 8x8 per thread.
// MODE 0: C = silu(acc)
// MODE 1: gate-merge epilogue.
// ============================================================================
template <int MODE>
__global__ __launch_bounds__(256) void gemm_k(
    const float* __restrict__ A, int lda,
    const float* __restrict__ B, int ldb,
    float* __restrict__ Cp, int ldc,
    int K,
    const float* __restrict__ bias,
    const float* __restrict__ attn,
    const float* __restrict__ irms,
    const float* __restrict__ won)
{
    __shared__ float As[16][132];
    __shared__ float Bs[16][132];
    const int tid = threadIdx.x;
    const int m0 = blockIdx.y * 128;
    const int n0 = blockIdx.x * 128;
    const int ty = tid >> 4, tx = tid & 15;

    float acc[8][8];
#pragma unroll
    for (int i = 0; i < 8; i++)
#pragma unroll
        for (int j = 0; j < 8; j++) acc[i][j] = 0.f;

    for (int k0 = 0; k0 < K; k0 += 16) {
#pragma unroll
        for (int it = 0; it < 2; it++) {
            int lin = tid + it * 256;
            int r = lin >> 2, c4 = (lin & 3) << 2;
            float4 av = *(const float4*)&A[(size_t)(m0 + r) * lda + k0 + c4];
            As[c4 + 0][r] = av.x;
            As[c4 + 1][r] = av.y;
            As[c4 + 2][r] = av.z;
            As[c4 + 3][r] = av.w;
            int rb = lin >> 5, cb = (lin & 31) << 2;
            *(float4*)&Bs[rb][cb] = *(const float4*)&B[(size_t)(k0 + rb) * ldb + n0 + cb];
        }
        __syncthreads();
#pragma unroll
        for (int kk = 0; kk < 16; kk++) {
            float a[8], b[8];
            *(float4*)&a[0] = *(float4*)&As[kk][ty * 4];
            *(float4*)&a[4] = *(float4*)&As[kk][64 + ty * 4];
            *(float4*)&b[0] = *(float4*)&Bs[kk][tx * 4];
            *(float4*)&b[4] = *(float4*)&Bs[kk][64 + tx * 4];
#pragma unroll
            for (int i = 0; i < 8; i++)
#pragma unroll
                for (int j = 0; j < 8; j++) acc[i][j] += a[i] * b[j];
        }
        __syncthreads();
    }

#pragma unroll
    for (int i = 0; i < 8; i++) {
        int m = m0 + ((i < 4) ? (ty * 4 + i) : (64 + ty * 4 + i - 4));
#pragma unroll
        for (int j = 0; j < 8; j++) {
            int n = n0 + ((j < 4) ? (tx * 4 + j) : (64 + tx * 4 + j - 4));
            float val = acc[i][j];
            if (MODE == 0) {
                val = silu(val);
            } else {
                float gz = val + bias[n];
                gz = silu(gz);
                float g = sigm(gz);
                float vv = A[(size_t)m * lda + n];
                float o = attn[(size_t)m * 256 + n] * irms[m] * won[n];
                val = g * vv + (1.f - g) * o;
            }
            Cp[(size_t)m * ldc + n] = val;
        }
    }
}

// ============================================================================
// width/sharpness projection: warp per row, N=8 outputs.
// ============================================================================
__global__ __launch_bounds__(256) void wp_k(
    const float* __restrict__ x, const float* __restrict__ W,
    const float* __restrict__ bias,
    float* __restrict__ width, float* __restrict__ sharp)
{
    int row = (blockIdx.x * 256 + threadIdx.x) >> 5;
    int lane = threadIdx.x & 31;
    if (row >= NROWS) return;
    const float* xr = x + (size_t)row * 256;
    float acc[8] = {0, 0, 0, 0, 0, 0, 0, 0};
    for (int k = lane; k < 256; k += 32) {
        float xv = xr[k];
#pragma unroll
        for (int j = 0; j < 8; j++) acc[j] += xv * W[k * 8 + j];
    }
#pragma unroll
    for (int off = 16; off; off >>= 1)
#pragma unroll
        for (int j = 0; j < 8; j++) acc[j] += __shfl_xor_sync(0xffffffffu, acc[j], off);
    if (lane == 0) {
#pragma unroll
        for (int j = 0; j < 4; j++) {
            float wr = silu(acc[j] + bias[j]);
            width[row * 4 + j] = sigm(wr) * 4.2426406871192851f + 0.5f;
            float sr = silu(acc[4 + j] + bias[4 + j]);
            sharp[row * 4 + j] = sigm(sr) * 9.5f + 0.5f;
        }
    }
}

// ============================================================================
// rmsnorm + rope on q and k: warp per (row, head).
// ============================================================================
__global__ __launch_bounds__(256) void normrope_k(
    const float* __restrict__ qkv,
    const float* __restrict__ wq, const float* __restrict__ wk,
    float* __restrict__ qr, float* __restrict__ kr)
{
    int g = (blockIdx.x * 256 + threadIdx.x) >> 5;
    int lane = threadIdx.x & 31;
    if (g >= NROWS * HEADS) return;
    int row = g >> 2, h = g & 3;
    const float* qp = qkv + (size_t)row * 768 + h * 64;
    float q1 = qp[lane], q2 = qp[lane + 32];
    float k1 = qp[256 + lane], k2 = qp[256 + lane + 32];
    float sq = q1 * q1 + q2 * q2;
    float sk = k1 * k1 + k2 * k2;
#pragma unroll
    for (int off = 16; off; off >>= 1) {
        sq += __shfl_xor_sync(0xffffffffu, sq, off);
        sk += __shfl_xor_sync(0xffffffffu, sk, off);
    }
    float qi = rsqrtf(sq * (1.f / 64.f) + 1e-6f);
    float ki = rsqrtf(sk * (1.f / 64.f) + 1e-6f);
    q1 *= qi * wq[lane];
    q2 *= qi * wq[lane + 32];
    k1 *= ki * wk[lane];
    k2 *= ki * wk[lane + 32];
    float freq = expf(-9.210340371976184f * (float)lane * (1.f / 32.f));
    float ang = (float)h * freq;
    float cs = cosf(ang), sn = sinf(ang);
    size_t o = (size_t)row * 256 + h * 64;
    qr[o + lane] = q1 * cs - q2 * sn;
    qr[o + lane + 32] = q1 * sn + q2 * cs;
    kr[o + lane] = k1 * cs - k2 * sn;
    kr[o + lane + 32] = k1 * sn + k2 * cs;
}

// ============================================================================
// Local attention. Block = (8x8 spatial tile, head, batch). 256 threads.
// K/V halo tiles in smem with PADDED row stride (68 floats) so consecutive
// spatial rows start 4 banks apart -> conflict-free QK, 2-way-max AV.
// QK: lane owns full 64-dim q, computes disjoint window subset {sub+4j}.
// ============================================================================
__global__ __launch_bounds__(256) void attn_k(
    const float* __restrict__ qr, const float* __restrict__ kr,
    const float* __restrict__ qkv,  // v = cols [512,768)
    const float* __restrict__ width, const float* __restrict__ sharp,
    float* __restrict__ out)
{
    extern __shared__ float sm[];
    float* ks = sm;                     // 196 * KST
    float* vs = sm + 196 * KST;         // 196 * KST
    float* sc = sm + 2 * 196 * KST;     // 64 * 52
    const int tile = blockIdx.x, h = blockIdx.y, b = blockIdx.z;
    const int ty0 = (tile >> 3) << 3;
    const int tx0 = (tile & 7) << 3;
    const int tid = threadIdx.x;

    // stage K/V halo (14x14 spatial x 64 dims, padded rows)
    for (int idx = tid; idx < 196 * 16; idx += 256) {
        int sp = idx >> 4, f = idx & 15;
        int yy = ty0 - 3 + sp / 14;
        int xx = tx0 - 3 + sp % 14;
        float4 kv = make_float4(0.f, 0.f, 0.f, 0.f);
        float4 vv = make_float4(0.f, 0.f, 0.f, 0.f);
        if (yy >= 0 && yy < GRIDW && xx >= 0 && xx < GRIDW) {
            int r = (b * GRIDW + yy) * GRIDW + xx;
            kv = *(const float4*)&kr[(size_t)r * 256 + h * 64 + f * 4];
            vv = *(const float4*)&qkv[(size_t)r * 768 + 512 + h * 64 + f * 4];
        }
        *(float4*)&ks[sp * KST + f * 4] = kv;
        *(float4*)&vs[sp * KST + f * 4] = vv;
    }
    __syncthreads();

    const int p = tid >> 2, sub = tid & 3;
    const int py = p >> 3, px = p & 7;
    const int row = (b * GRIDW + ty0 + py) * GRIDW + tx0 + px;

    const float wd = width[row * 4 + h];
    const float sh = sharp[row * 4 + h];

    // ---- QK phase: full q in registers, disjoint windows per lane ----
    {
        float q[64];
#pragma unroll
        for (int i = 0; i < 16; i++)
            *(float4*)&q[i * 4] = *(const float4*)&qr[(size_t)row * 256 + h * 64 + i * 4];

#pragma unroll
        for (int j = 0; j < 13; j++) {
            int w = sub + 4 * j;
            if (w < 49) {
                int wy = w / 7, wx = w % 7;
                const float* kp = &ks[((py + wy) * 14 + px + wx) * KST];
                float s0 = 0.f, s1 = 0.f, s2 = 0.f, s3 = 0.f;
#pragma unroll
                for (int i = 0; i < 16; i++) {
                    float4 kv = *(const float4*)&kp[i * 4];
                    s0 += q[i * 4 + 0] * kv.x;
                    s1 += q[i * 4 + 1] * kv.y;
                    s2 += q[i * 4 + 2] * kv.z;
                    s3 += q[i * 4 + 3] * kv.w;
                }
                float s = (s0 + s1) + (s2 + s3);
                float dy = (float)(wy - 3), dx = (float)(wx - 3);
                float rd = sqrtf(dy * dy + dx * dx);
                float soft = sigm((wd - rd) * sh);
                sc[p * 52 + w] = s * 0.125f - (1.f - soft) * 10000.f;
            }
        }
    }
    __syncwarp();

    // ---- softmax over 49 (4 lanes cooperate) ----
    float mx = -1e30f;
    for (int w = sub; w < 49; w += 4) mx = fmaxf(mx, sc[p * 52 + w]);
    mx = fmaxf(mx, __shfl_xor_sync(0xffffffffu, mx, 1));
    mx = fmaxf(mx, __shfl_xor_sync(0xffffffffu, mx, 2));
    float sum = 0.f;
    for (int w = sub; w < 49; w += 4) {
        float e = expf(sc[p * 52 + w] - mx);
        sc[p * 52 + w] = e;
        sum += e;
    }
    sum += __shfl_xor_sync(0xffffffffu, sum, 1);
    sum += __shfl_xor_sync(0xffffffffu, sum, 2);
    __syncwarp();
    float inv = 1.f / sum;

    // ---- AV phase: thread owns (p, 16 dims) ----
    float o[16];
#pragma unroll
    for (int i = 0; i < 16; i++) o[i] = 0.f;
    for (int w = 0; w < 49; w++) {
        float a = sc[p * 52 + w];
        const float* vp = &vs[((py + w / 7) * 14 + px + w % 7) * KST + sub * 16];
#pragma unroll
        for (int i = 0; i < 16; i++) o[i] += a * vp[i];
    }
#pragma unroll
    for (int i = 0; i < 4; i++) {
        float4 r = make_float4(o[i * 4] * inv, o[i * 4 + 1] * inv, o[i * 4 + 2] * inv, o[i * 4 + 3] * inv);
        *(float4*)&out[(size_t)row * 256 + h * 64 + sub * 16 + i * 4] = r;
    }
}

// ============================================================================
// inv-RMS per row of attention output.
// ============================================================================
__global__ __launch_bounds__(256) void irms_k(
    const float* __restrict__ attn, float* __restrict__ irms)
{
    int row = (blockIdx.x * 256 + threadIdx.x) >> 5;
    int lane = threadIdx.x & 31;
    if (row >= NROWS) return;
    const float* a = attn + (size_t)row * 256;
    float s = 0.f;
    for (int k = lane; k < 256; k += 32) {
        float v = a[k];
        s += v * v;
    }
#pragma unroll
    for (int off = 16; off; off >>= 1) s += __shfl_xor_sync(0xffffffffu, s, off);
    if (lane == 0) irms[row] = rsqrtf(s * (1.f / 256.f) + 1e-6f);
}

// ============================================================================
extern "C" void kernel_launch(void* const* d_in, const int* in_sizes, int n_in,
                              void* d_out, int out_size)
{
    const float* x      = (const float*)d_in[0];
    const float* W_qkv  = (const float*)d_in[1];
    const float* w_qn   = (const float*)d_in[2];
    const float* w_kn   = (const float*)d_in[3];
    const float* W_wp   = (const float*)d_in[4];
    const float* b_wp   = (const float*)d_in[5];
    const float* w_on   = (const float*)d_in[6];
    const float* W_out  = (const float*)d_in[7];
    const float* W_gate = (const float*)d_in[8];
    const float* b_gate = (const float*)d_in[9];
    float* out = (float*)d_out;

    float *qkv, *qr, *kr, *wd, *sh, *attn, *irms, *merged;
    cudaGetSymbolAddress((void**)&qkv, g_qkv);
    cudaGetSymbolAddress((void**)&qr, g_qr);
    cudaGetSymbolAddress((void**)&kr, g_kr);
    cudaGetSymbolAddress((void**)&wd, g_width);
    cudaGetSymbolAddress((void**)&sh, g_sharp);
    cudaGetSymbolAddress((void**)&attn, g_attn);
    cudaGetSymbolAddress((void**)&irms, g_irms);
    cudaGetSymbolAddress((void**)&merged, g_merged);

    const int SMEM_ATTN = (2 * 196 * KST + 64 * 52) * 4;  // 119,936 B
    cudaFuncSetAttribute(attn_k, cudaFuncAttributeMaxDynamicSharedMemorySize, SMEM_ATTN);

    // 1) qkv = silu(x @ W_qkv)   [8192 x 768 x 256]
    gemm_k<0><<<dim3(6, 64), 256>>>(x, 256, W_qkv, 768, qkv, 768, 256,
                                    nullptr, nullptr, nullptr, nullptr);
    // 2) width/sharpness
    wp_k<<<NROWS / 8, 256>>>(x, W_wp, b_wp, wd, sh);
    // 3) rmsnorm + rope on q,k
    normrope_k<<<NROWS * HEADS / 8, 256>>>(qkv, w_qn, w_kn, qr, kr);
    // 4) local attention
    attn_k<<<dim3(64, HEADS, 2), 256, SMEM_ATTN>>>(qr, kr, qkv, wd, sh, attn);
    // 5) inv-rms of attention output
    irms_k<<<NROWS / 8, 256>>>(attn, irms);
    // 6) merged = gate*v + (1-gate)*rmsnorm(attn)   [8192 x 256 x 256]
    gemm_k<1><<<dim3(2, 64), 256>>>(qkv + 512, 768, W_gate, 256, merged, 256, 256,
                                    b_gate, attn, irms, w_on);
    // 7) out = silu(merged @ W_out)                 [8192 x 256 x 256]
    gemm_k<0><<<dim3(2, 64), 256>>>(merged, 256, W_out, 256, out, 256, 256,
                                    nullptr, nullptr, nullptr, nullptr);
}

// round 5
// speedup vs baseline: 1.3688x; 1.1349x over previous
#include <cuda_runtime.h>
#include <math.h>

#define NROWS 8192   // B*Hs*Ws = 2*64*64
#define CDIM  256
#define HEADS 4
#define HD    64
#define GRIDW 64     // Hs = Ws
#define KST   68     // padded smem row stride (floats): 68%32=4 bank stagger, 16B-aligned rows

// -------- scratch (no allocations allowed) --------
__device__ float g_qkv[NROWS * 768];
__device__ float g_qr[NROWS * CDIM];
__device__ float g_kr[NROWS * CDIM];
__device__ float g_width[NROWS * HEADS];
__device__ float g_sharp[NROWS * HEADS];
__device__ float g_attn[NROWS * CDIM];
__device__ float g_irms[NROWS];
__device__ float g_merged[NROWS * CDIM];

__device__ __forceinline__ float sigm(float x) { return 1.f / (1.f + expf(-x)); }
__device__ __forceinline__ float silu(float x) { return x / (1.f + expf(-x)); }

__device__ __forceinline__ unsigned long long pack_dup(float a) {
    unsigned long long r;
    unsigned int u = __float_as_uint(a);
    asm("mov.b64 %0, {%1, %1};" : "=l"(r) : "r"(u));
    return r;
}
__device__ __forceinline__ void fma2(unsigned long long& d, unsigned long long a, unsigned long long b) {
    asm("fma.rn.f32x2 %0, %1, %2, %0;" : "+l"(d) : "l"(a), "l"(b));
}
__device__ __forceinline__ void unpack2(unsigned long long v, float& lo, float& hi) {
    unsigned int l, h;
    asm("mov.b64 {%0, %1}, %2;" : "=r"(l), "=r"(h) : "l"(v));
    lo = __uint_as_float(l);
    hi = __uint_as_float(h);
}

// ============================================================================
// fp32 SGEMM with packed FFMA2 math: 128x128 tile, BK=16, 256 threads,
// 8 rows x 4 column-pairs (= 8x8 fp32) per thread.
// MODE 0: C = silu(acc)
// MODE 1: gate-merge epilogue:
//   g = sigmoid(silu(acc + bias[n]))
//   C = g * A[m*lda+n] + (1-g) * attn[m*256+n]*irms[m]*won[n]
// ============================================================================
template <int MODE>
__global__ __launch_bounds__(256) void gemm_k(
    const float* __restrict__ A, int lda,
    const float* __restrict__ B, int ldb,
    float* __restrict__ Cp, int ldc,
    int K,
    const float* __restrict__ bias,
    const float* __restrict__ attn,
    const float* __restrict__ irms,
    const float* __restrict__ won)
{
    __shared__ float As[16][132];
    __shared__ float Bs[16][132];
    const int tid = threadIdx.x;
    const int m0 = blockIdx.y * 128;
    const int n0 = blockIdx.x * 128;
    const int ty = tid >> 4, tx = tid & 15;

    unsigned long long acc[8][4];
#pragma unroll
    for (int i = 0; i < 8; i++)
#pragma unroll
        for (int j = 0; j < 4; j++) acc[i][j] = 0ull;

    for (int k0 = 0; k0 < K; k0 += 16) {
#pragma unroll
        for (int it = 0; it < 2; it++) {
            int lin = tid + it * 256;
            int r = lin >> 2, c4 = (lin & 3) << 2;
            float4 av = *(const float4*)&A[(size_t)(m0 + r) * lda + k0 + c4];
            As[c4 + 0][r] = av.x;
            As[c4 + 1][r] = av.y;
            As[c4 + 2][r] = av.z;
            As[c4 + 3][r] = av.w;
            int rb = lin >> 5, cb = (lin & 31) << 2;
            *(float4*)&Bs[rb][cb] = *(const float4*)&B[(size_t)(k0 + rb) * ldb + n0 + cb];
        }
        __syncthreads();
#pragma unroll
        for (int kk = 0; kk < 16; kk++) {
            float a[8];
            *(float4*)&a[0] = *(float4*)&As[kk][ty * 4];
            *(float4*)&a[4] = *(float4*)&As[kk][64 + ty * 4];
            unsigned long long br[4];
            br[0] = *(const unsigned long long*)&Bs[kk][tx * 4];
            br[1] = *(const unsigned long long*)&Bs[kk][tx * 4 + 2];
            br[2] = *(const unsigned long long*)&Bs[kk][64 + tx * 4];
            br[3] = *(const unsigned long long*)&Bs[kk][64 + tx * 4 + 2];
            unsigned long long ar[8];
#pragma unroll
            for (int i = 0; i < 8; i++) ar[i] = pack_dup(a[i]);
#pragma unroll
            for (int i = 0; i < 8; i++)
#pragma unroll
                for (int j = 0; j < 4; j++) fma2(acc[i][j], ar[i], br[j]);
        }
        __syncthreads();
    }

#pragma unroll
    for (int i = 0; i < 8; i++) {
        int m = m0 + ((i < 4) ? (ty * 4 + i) : (64 + ty * 4 + i - 4));
#pragma unroll
        for (int j = 0; j < 4; j++) {
            // column pair (2j, 2j+1): j<2 -> n = tx*4 + 2j; j>=2 -> n = 64 + tx*4 + 2j-4
            int n = n0 + ((j < 2) ? (tx * 4 + 2 * j) : (64 + tx * 4 + 2 * j - 4));
            float vlo, vhi;
            unpack2(acc[i][j], vlo, vhi);
            float r0, r1;
            if (MODE == 0) {
                r0 = silu(vlo);
                r1 = silu(vhi);
            } else {
                float g0 = sigm(silu(vlo + bias[n]));
                float g1 = sigm(silu(vhi + bias[n + 1]));
                float vv0 = A[(size_t)m * lda + n];
                float vv1 = A[(size_t)m * lda + n + 1];
                float ir = irms[m];
                float o0 = attn[(size_t)m * 256 + n] * ir * won[n];
                float o1 = attn[(size_t)m * 256 + n + 1] * ir * won[n + 1];
                r0 = g0 * vv0 + (1.f - g0) * o0;
                r1 = g1 * vv1 + (1.f - g1) * o1;
            }
            *(float2*)&Cp[(size_t)m * ldc + n] = make_float2(r0, r1);
        }
    }
}

// ============================================================================
// width/sharpness projection: warp per row, N=8 outputs.
// ============================================================================
__global__ __launch_bounds__(256) void wp_k(
    const float* __restrict__ x, const float* __restrict__ W,
    const float* __restrict__ bias,
    float* __restrict__ width, float* __restrict__ sharp)
{
    int row = (blockIdx.x * 256 + threadIdx.x) >> 5;
    int lane = threadIdx.x & 31;
    if (row >= NROWS) return;
    const float* xr = x + (size_t)row * 256;
    float acc[8] = {0, 0, 0, 0, 0, 0, 0, 0};
    for (int k = lane; k < 256; k += 32) {
        float xv = xr[k];
#pragma unroll
        for (int j = 0; j < 8; j++) acc[j] += xv * W[k * 8 + j];
    }
#pragma unroll
    for (int off = 16; off; off >>= 1)
#pragma unroll
        for (int j = 0; j < 8; j++) acc[j] += __shfl_xor_sync(0xffffffffu, acc[j], off);
    if (lane == 0) {
#pragma unroll
        for (int j = 0; j < 4; j++) {
            float wr = silu(acc[j] + bias[j]);
            width[row * 4 + j] = sigm(wr) * 4.2426406871192851f + 0.5f;
            float sr = silu(acc[4 + j] + bias[4 + j]);
            sharp[row * 4 + j] = sigm(sr) * 9.5f + 0.5f;
        }
    }
}

// ============================================================================
// rmsnorm + rope on q and k: warp per (row, head).
// ============================================================================
__global__ __launch_bounds__(256) void normrope_k(
    const float* __restrict__ qkv,
    const float* __restrict__ wq, const float* __restrict__ wk,
    float* __restrict__ qr, float* __restrict__ kr)
{
    int g = (blockIdx.x * 256 + threadIdx.x) >> 5;
    int lane = threadIdx.x & 31;
    if (g >= NROWS * HEADS) return;
    int row = g >> 2, h = g & 3;
    const float* qp = qkv + (size_t)row * 768 + h * 64;
    float q1 = qp[lane], q2 = qp[lane + 32];
    float k1 = qp[256 + lane], k2 = qp[256 + lane + 32];
    float sq = q1 * q1 + q2 * q2;
    float sk = k1 * k1 + k2 * k2;
#pragma unroll
    for (int off = 16; off; off >>= 1) {
        sq += __shfl_xor_sync(0xffffffffu, sq, off);
        sk += __shfl_xor_sync(0xffffffffu, sk, off);
    }
    float qi = rsqrtf(sq * (1.f / 64.f) + 1e-6f);
    float ki = rsqrtf(sk * (1.f / 64.f) + 1e-6f);
    q1 *= qi * wq[lane];
    q2 *= qi * wq[lane + 32];
    k1 *= ki * wk[lane];
    k2 *= ki * wk[lane + 32];
    float freq = expf(-9.210340371976184f * (float)lane * (1.f / 32.f));
    float ang = (float)h * freq;
    float cs = cosf(ang), sn = sinf(ang);
    size_t o = (size_t)row * 256 + h * 64;
    qr[o + lane] = q1 * cs - q2 * sn;
    qr[o + lane + 32] = q1 * sn + q2 * cs;
    kr[o + lane] = k1 * cs - k2 * sn;
    kr[o + lane + 32] = k1 * sn + k2 * cs;
}

// ============================================================================
// Local attention. Block = (8x8 spatial tile, head, batch). 256 threads.
// K/V halo in smem (stride 68 -> staggered banks). NO score smem: scores in
// registers (13/lane), softmax via 4-lane shuffles, AV weights broadcast with
// width-4 shuffles in a fully unrolled loop. smem=106.6KB -> 2 CTAs/SM.
// ============================================================================
__global__ __launch_bounds__(256, 2) void attn_k(
    const float* __restrict__ qr, const float* __restrict__ kr,
    const float* __restrict__ qkv,  // v = cols [512,768)
    const float* __restrict__ width, const float* __restrict__ sharp,
    float* __restrict__ out)
{
    extern __shared__ float sm[];
    float* ks = sm;                     // 196 * KST
    float* vs = sm + 196 * KST;         // 196 * KST
    const int tile = blockIdx.x, h = blockIdx.y, b = blockIdx.z;
    const int ty0 = (tile >> 3) << 3;
    const int tx0 = (tile & 7) << 3;
    const int tid = threadIdx.x;

    // stage K/V halo (14x14 spatial x 64 dims, padded rows)
    for (int idx = tid; idx < 196 * 16; idx += 256) {
        int sp = idx >> 4, f = idx & 15;
        int yy = ty0 - 3 + sp / 14;
        int xx = tx0 - 3 + sp % 14;
        float4 kv = make_float4(0.f, 0.f, 0.f, 0.f);
        float4 vv = make_float4(0.f, 0.f, 0.f, 0.f);
        if (yy >= 0 && yy < GRIDW && xx >= 0 && xx < GRIDW) {
            int r = (b * GRIDW + yy) * GRIDW + xx;
            kv = *(const float4*)&kr[(size_t)r * 256 + h * 64 + f * 4];
            vv = *(const float4*)&qkv[(size_t)r * 768 + 512 + h * 64 + f * 4];
        }
        *(float4*)&ks[sp * KST + f * 4] = kv;
        *(float4*)&vs[sp * KST + f * 4] = vv;
    }
    __syncthreads();

    const int p = tid >> 2, sub = tid & 3;
    const int py = p >> 3, px = p & 7;
    const int row = (b * GRIDW + ty0 + py) * GRIDW + tx0 + px;

    const float wd = width[row * 4 + h];
    const float sh = sharp[row * 4 + h];

    // ---- QK phase: full q in registers, disjoint windows per lane;
    //      scores stay in registers sr[13] (w = sub + 4*j) ----
    float sr[13];
    {
        float q[64];
#pragma unroll
        for (int i = 0; i < 16; i++)
            *(float4*)&q[i * 4] = *(const float4*)&qr[(size_t)row * 256 + h * 64 + i * 4];

#pragma unroll
        for (int j = 0; j < 13; j++) {
            int w = sub + 4 * j;
            if (w < 49) {
                int wy = w / 7, wx = w % 7;
                const float* kp = &ks[((py + wy) * 14 + px + wx) * KST];
                float s0 = 0.f, s1 = 0.f, s2 = 0.f, s3 = 0.f;
#pragma unroll
                for (int i = 0; i < 16; i++) {
                    float4 kv = *(const float4*)&kp[i * 4];
                    s0 += q[i * 4 + 0] * kv.x;
                    s1 += q[i * 4 + 1] * kv.y;
                    s2 += q[i * 4 + 2] * kv.z;
                    s3 += q[i * 4 + 3] * kv.w;
                }
                float s = (s0 + s1) + (s2 + s3);
                float dy = (float)(wy - 3), dx = (float)(wx - 3);
                float rd = sqrtf(dy * dy + dx * dx);
                float soft = sigm((wd - rd) * sh);
                sr[j] = s * 0.125f - (1.f - soft) * 10000.f;
            } else {
                sr[j] = -1e30f;   // exp -> 0
            }
        }
    }

    // ---- softmax over 49: local max/sum + 4-lane shuffle reduce ----
    float mx = sr[0];
#pragma unroll
    for (int j = 1; j < 13; j++) mx = fmaxf(mx, sr[j]);
    mx = fmaxf(mx, __shfl_xor_sync(0xffffffffu, mx, 1));
    mx = fmaxf(mx, __shfl_xor_sync(0xffffffffu, mx, 2));
    float sum = 0.f;
#pragma unroll
    for (int j = 0; j < 13; j++) {
        float e = expf(sr[j] - mx);
        sr[j] = e;
        sum += e;
    }
    sum += __shfl_xor_sync(0xffffffffu, sum, 1);
    sum += __shfl_xor_sync(0xffffffffu, sum, 2);
    float inv = 1.f / sum;

    // ---- AV phase: thread owns (p, 16 dims); weight broadcast via shfl ----
    float o[16];
#pragma unroll
    for (int i = 0; i < 16; i++) o[i] = 0.f;
#pragma unroll
    for (int w = 0; w < 49; w++) {
        const int j = w >> 2, owner = w & 3;
        float a = __shfl_sync(0xffffffffu, sr[j], owner, 4);
        const float* vp = &vs[((py + w / 7) * 14 + px + w % 7) * KST + sub * 16];
#pragma unroll
        for (int i = 0; i < 16; i++) o[i] += a * vp[i];
    }
#pragma unroll
    for (int i = 0; i < 4; i++) {
        float4 r = make_float4(o[i * 4] * inv, o[i * 4 + 1] * inv, o[i * 4 + 2] * inv, o[i * 4 + 3] * inv);
        *(float4*)&out[(size_t)row * 256 + h * 64 + sub * 16 + i * 4] = r;
    }
}

// ============================================================================
// inv-RMS per row of attention output.
// ============================================================================
__global__ __launch_bounds__(256) void irms_k(
    const float* __restrict__ attn, float* __restrict__ irms)
{
    int row = (blockIdx.x * 256 + threadIdx.x) >> 5;
    int lane = threadIdx.x & 31;
    if (row >= NROWS) return;
    const float* a = attn + (size_t)row * 256;
    float s = 0.f;
    for (int k = lane; k < 256; k += 32) {
        float v = a[k];
        s += v * v;
    }
#pragma unroll
    for (int off = 16; off; off >>= 1) s += __shfl_xor_sync(0xffffffffu, s, off);
    if (lane == 0) irms[row] = rsqrtf(s * (1.f / 256.f) + 1e-6f);
}

// ============================================================================
extern "C" void kernel_launch(void* const* d_in, const int* in_sizes, int n_in,
                              void* d_out, int out_size)
{
    const float* x      = (const float*)d_in[0];
    const float* W_qkv  = (const float*)d_in[1];
    const float* w_qn   = (const float*)d_in[2];
    const float* w_kn   = (const float*)d_in[3];
    const float* W_wp   = (const float*)d_in[4];
    const float* b_wp   = (const float*)d_in[5];
    const float* w_on   = (const float*)d_in[6];
    const float* W_out  = (const float*)d_in[7];
    const float* W_gate = (const float*)d_in[8];
    const float* b_gate = (const float*)d_in[9];
    float* out = (float*)d_out;

    float *qkv, *qr, *kr, *wd, *sh, *attn, *irms, *merged;
    cudaGetSymbolAddress((void**)&qkv, g_qkv);
    cudaGetSymbolAddress((void**)&qr, g_qr);
    cudaGetSymbolAddress((void**)&kr, g_kr);
    cudaGetSymbolAddress((void**)&wd, g_width);
    cudaGetSymbolAddress((void**)&sh, g_sharp);
    cudaGetSymbolAddress((void**)&attn, g_attn);
    cudaGetSymbolAddress((void**)&irms, g_irms);
    cudaGetSymbolAddress((void**)&merged, g_merged);

    const int SMEM_ATTN = (2 * 196 * KST) * 4;  // 106,624 B -> 2 CTAs/SM
    cudaFuncSetAttribute(attn_k, cudaFuncAttributeMaxDynamicSharedMemorySize, SMEM_ATTN);

    // 1) qkv = silu(x @ W_qkv)   [8192 x 768 x 256]
    gemm_k<0><<<dim3(6, 64), 256>>>(x, 256, W_qkv, 768, qkv, 768, 256,
                                    nullptr, nullptr, nullptr, nullptr);
    // 2) width/sharpness
    wp_k<<<NROWS / 8, 256>>>(x, W_wp, b_wp, wd, sh);
    // 3) rmsnorm + rope on q,k
    normrope_k<<<NROWS * HEADS / 8, 256>>>(qkv, w_qn, w_kn, qr, kr);
    // 4) local attention
    attn_k<<<dim3(64, HEADS, 2), 256, SMEM_ATTN>>>(qr, kr, qkv, wd, sh, attn);
    // 5) inv-rms of attention output
    irms_k<<<NROWS / 8, 256>>>(attn, irms);
    // 6) merged = gate*v + (1-gate)*rmsnorm(attn)   [8192 x 256 x 256]
    gemm_k<1><<<dim3(2, 64), 256>>>(qkv + 512, 768, W_gate, 256, merged, 256, 256,
                                    b_gate, attn, irms, w_on);
    // 7) out = silu(merged @ W_out)                 [8192 x 256 x 256]
    gemm_k<0><<<dim3(2, 64), 256>>>(merged, 256, W_out, 256, out, 256, 256,
                                    nullptr, nullptr, nullptr, nullptr);
}

// round 7
// speedup vs baseline: 1.3725x; 1.0027x over previous
#include <cuda_runtime.h>
#include <cuda_bf16.h>
#include <mma.h>
#include <math.h>
#include <stdint.h>

using namespace nvcuda;

#define NROWS 8192   // B*Hs*Ws = 2*64*64
#define CDIM  256
#define HEADS 4
#define HD    64
#define GRIDW 64     // Hs = Ws
#define KST   68     // attn smem row stride (floats)
#define ASTR  48     // gemm staging smem stride (bf16)
#define CSTR  68     // gemm epilogue smem stride (fp32)

// -------- scratch (no allocations allowed) --------
__device__ __align__(256) float g_qkv[NROWS * 768];
__device__ __align__(256) float g_qr[NROWS * CDIM];
__device__ __align__(256) float g_kr[NROWS * CDIM];
__device__ __align__(256) float g_width[NROWS * HEADS];
__device__ __align__(256) float g_sharp[NROWS * HEADS];
__device__ __align__(256) float g_attn[NROWS * CDIM];
__device__ __align__(256) float g_irms[NROWS];
// bf16 split operands
__device__ __align__(256) __nv_bfloat16 g_xh[NROWS * 256];
__device__ __align__(256) __nv_bfloat16 g_xl[NROWS * 256];
__device__ __align__(256) __nv_bfloat16 g_vh[NROWS * 256];
__device__ __align__(256) __nv_bfloat16 g_vl[NROWS * 256];
__device__ __align__(256) __nv_bfloat16 g_mh[NROWS * 256];
__device__ __align__(256) __nv_bfloat16 g_ml[NROWS * 256];
// weights transposed to [N][K] bf16 hi/lo
__device__ __align__(256) __nv_bfloat16 g_wqh[768 * 256];
__device__ __align__(256) __nv_bfloat16 g_wql[768 * 256];
__device__ __align__(256) __nv_bfloat16 g_wgh[256 * 256];
__device__ __align__(256) __nv_bfloat16 g_wgl[256 * 256];
__device__ __align__(256) __nv_bfloat16 g_woh[256 * 256];
__device__ __align__(256) __nv_bfloat16 g_wol[256 * 256];

__device__ __forceinline__ float sigm(float x) { return 1.f / (1.f + expf(-x)); }
__device__ __forceinline__ float silu(float x) { return x / (1.f + expf(-x)); }

// ============================================================================
// split helpers
// ============================================================================
__global__ __launch_bounds__(256) void xsplit_k(
    const float* __restrict__ x, __nv_bfloat16* __restrict__ xh,
    __nv_bfloat16* __restrict__ xl)
{
    int idx = blockIdx.x * 256 + threadIdx.x;
    float v = x[idx];
    __nv_bfloat16 h = __float2bfloat16(v);
    xh[idx] = h;
    xl[idx] = __float2bfloat16(v - __bfloat162float(h));
}

// W [K,N] fp32 row-major -> Wt [N,K] bf16 hi/lo
__global__ __launch_bounds__(256) void wsplit_k(
    const float* __restrict__ W, int K, int N,
    __nv_bfloat16* __restrict__ th, __nv_bfloat16* __restrict__ tl)
{
    int idx = blockIdx.x * 256 + threadIdx.x;
    if (idx >= K * N) return;
    int n = idx / K, k = idx - n * K;
    float v = W[(size_t)k * N + n];
    __nv_bfloat16 h = __float2bfloat16(v);
    th[idx] = h;
    tl[idx] = __float2bfloat16(v - __bfloat162float(h));
}

// ============================================================================
// Tensor-core GEMM via wmma (bf16 m16n16k16, fp32 accum) with 2-term bf16
// split: D = Ah*Bh + Ah*Bl + Al*Bh.
// CTA = 128(M) x 128(N), 8 warps (4x2 grid), warp tile 32x64 = 2x4 atoms.
// A: [M][256] bf16 hi/lo row-major; B: [N][256] bf16 hi/lo (i.e. W^T).
// MODE 0 (qkv): C=silu(acc) fp32 (ldc=768); for n>=512 also emit v bf16 split.
// MODE 1 (gate): g=sigm(silu(acc+bias[n])); merged=g*v+(1-g)*attn*irms*won;
//                emit merged bf16 split only.
// MODE 2 (out):  C=silu(acc) fp32 (ldc=256).
// ============================================================================
template <int MODE>
__global__ __launch_bounds__(256) void tc_gemm(
    const __nv_bfloat16* __restrict__ Ah, const __nv_bfloat16* __restrict__ Al,
    const __nv_bfloat16* __restrict__ Bh, const __nv_bfloat16* __restrict__ Bl,
    float* __restrict__ Cp, int ldc,
    const float* __restrict__ bias, const float* __restrict__ qkv,
    const float* __restrict__ attn, const float* __restrict__ irms,
    const float* __restrict__ won,
    __nv_bfloat16* __restrict__ so_h, __nv_bfloat16* __restrict__ so_l)
{
    extern __shared__ char smem[];
    __nv_bfloat16* Ash = (__nv_bfloat16*)smem;          // 128*ASTR
    __nv_bfloat16* Asl = Ash + 128 * ASTR;
    __nv_bfloat16* Bsh = Asl + 128 * ASTR;
    __nv_bfloat16* Bsl = Bsh + 128 * ASTR;

    const int tid = threadIdx.x, wid = tid >> 5, lane = tid & 31;
    const int n0 = blockIdx.x * 128, m0 = blockIdx.y * 128;
    const int wm = wid & 3, wn = wid >> 2;   // warp tile: rows wm*32, cols wn*64

    wmma::fragment<wmma::accumulator, 16, 16, 16, float> acc[2][4];
#pragma unroll
    for (int mi = 0; mi < 2; mi++)
#pragma unroll
        for (int ni = 0; ni < 4; ni++) wmma::fill_fragment(acc[mi][ni], 0.f);

    for (int kc = 0; kc < 8; kc++) {
        // stage Ah/Al/Bh/Bl tiles: 128 rows x 32 cols each
#pragma unroll
        for (int it = 0; it < 8; it++) {
            int idx = tid + it * 256;
            int which = idx >> 9, t = idx & 511;
            int row = t >> 2, c8 = (t & 3) << 3;
            const __nv_bfloat16* gp;
            __nv_bfloat16* sp;
            if (which == 0)      { gp = Ah + (size_t)(m0 + row) * 256 + kc * 32 + c8; sp = Ash; }
            else if (which == 1) { gp = Al + (size_t)(m0 + row) * 256 + kc * 32 + c8; sp = Asl; }
            else if (which == 2) { gp = Bh + (size_t)(n0 + row) * 256 + kc * 32 + c8; sp = Bsh; }
            else                 { gp = Bl + (size_t)(n0 + row) * 256 + kc * 32 + c8; sp = Bsl; }
            *(uint4*)&sp[row * ASTR + c8] = *(const uint4*)gp;
        }
        __syncthreads();

#pragma unroll
        for (int kk = 0; kk < 32; kk += 16) {
            wmma::fragment<wmma::matrix_b, 16, 16, 16, __nv_bfloat16, wmma::col_major> bh[4], bl[4];
#pragma unroll
            for (int ni = 0; ni < 4; ni++) {
                wmma::load_matrix_sync(bh[ni], &Bsh[(wn * 64 + ni * 16) * ASTR + kk], ASTR);
                wmma::load_matrix_sync(bl[ni], &Bsl[(wn * 64 + ni * 16) * ASTR + kk], ASTR);
            }
#pragma unroll
            for (int mi = 0; mi < 2; mi++) {
                wmma::fragment<wmma::matrix_a, 16, 16, 16, __nv_bfloat16, wmma::row_major> ah, al;
                wmma::load_matrix_sync(ah, &Ash[(wm * 32 + mi * 16) * ASTR + kk], ASTR);
                wmma::load_matrix_sync(al, &Asl[(wm * 32 + mi * 16) * ASTR + kk], ASTR);
#pragma unroll
                for (int ni = 0; ni < 4; ni++) {
                    wmma::mma_sync(acc[mi][ni], ah, bh[ni], acc[mi][ni]);
                    wmma::mma_sync(acc[mi][ni], ah, bl[ni], acc[mi][ni]);
                    wmma::mma_sync(acc[mi][ni], al, bh[ni], acc[mi][ni]);
                }
            }
        }
        __syncthreads();
    }

    // epilogue: dump frags to per-warp smem region, then fused elementwise
    float* Cs = (float*)smem;
#pragma unroll
    for (int mi = 0; mi < 2; mi++)
#pragma unroll
        for (int ni = 0; ni < 4; ni++)
            wmma::store_matrix_sync(&Cs[wid * 32 * CSTR + mi * 16 * CSTR + ni * 16],
                                    acc[mi][ni], CSTR, wmma::mem_row_major);
    __syncwarp();

    for (int i = lane; i < 32 * 64; i += 32) {
        int r = i >> 6, c = i & 63;
        float v = Cs[wid * 32 * CSTR + r * CSTR + c];
        int m = m0 + wm * 32 + r;
        int n = n0 + wn * 64 + c;
        if (MODE == 0) {
            float s = silu(v);
            Cp[(size_t)m * ldc + n] = s;
            if (n >= 512) {
                int vo = m * 256 + n - 512;
                __nv_bfloat16 h = __float2bfloat16(s);
                so_h[vo] = h;
                so_l[vo] = __float2bfloat16(s - __bfloat162float(h));
            }
        } else if (MODE == 1) {
            float g = sigm(silu(v + bias[n]));
            float vv = qkv[(size_t)m * 768 + 512 + n];
            float o = attn[(size_t)m * 256 + n] * irms[m] * won[n];
            float merged = g * vv + (1.f - g) * o;
            __nv_bfloat16 h = __float2bfloat16(merged);
            so_h[m * 256 + n] = h;
            so_l[m * 256 + n] = __float2bfloat16(merged - __bfloat162float(h));
        } else {
            Cp[(size_t)m * ldc + n] = silu(v);
        }
    }
}

// ============================================================================
// width/sharpness projection: warp per row, N=8 outputs.
// ============================================================================
__global__ __launch_bounds__(256) void wp_k(
    const float* __restrict__ x, const float* __restrict__ W,
    const float* __restrict__ bias,
    float* __restrict__ width, float* __restrict__ sharp)
{
    int row = (blockIdx.x * 256 + threadIdx.x) >> 5;
    int lane = threadIdx.x & 31;
    if (row >= NROWS) return;
    const float* xr = x + (size_t)row * 256;
    float acc[8] = {0, 0, 0, 0, 0, 0, 0, 0};
    for (int k = lane; k < 256; k += 32) {
        float xv = xr[k];
#pragma unroll
        for (int j = 0; j < 8; j++) acc[j] += xv * W[k * 8 + j];
    }
#pragma unroll
    for (int off = 16; off; off >>= 1)
#pragma unroll
        for (int j = 0; j < 8; j++) acc[j] += __shfl_xor_sync(0xffffffffu, acc[j], off);
    if (lane == 0) {
#pragma unroll
        for (int j = 0; j < 4; j++) {
            float wr = silu(acc[j] + bias[j]);
            width[row * 4 + j] = sigm(wr) * 4.2426406871192851f + 0.5f;
            float sr = silu(acc[4 + j] + bias[4 + j]);
            sharp[row * 4 + j] = sigm(sr) * 9.5f + 0.5f;
        }
    }
}

// ============================================================================
// rmsnorm + rope on q and k: warp per (row, head).
// ============================================================================
__global__ __launch_bounds__(256) void normrope_k(
    const float* __restrict__ qkv,
    const float* __restrict__ wq, const float* __restrict__ wk,
    float* __restrict__ qr, float* __restrict__ kr)
{
    int g = (blockIdx.x * 256 + threadIdx.x) >> 5;
    int lane = threadIdx.x & 31;
    if (g >= NROWS * HEADS) return;
    int row = g >> 2, h = g & 3;
    const float* qp = qkv + (size_t)row * 768 + h * 64;
    float q1 = qp[lane], q2 = qp[lane + 32];
    float k1 = qp[256 + lane], k2 = qp[256 + lane + 32];
    float sq = q1 * q1 + q2 * q2;
    float sk = k1 * k1 + k2 * k2;
#pragma unroll
    for (int off = 16; off; off >>= 1) {
        sq += __shfl_xor_sync(0xffffffffu, sq, off);
        sk += __shfl_xor_sync(0xffffffffu, sk, off);
    }
    float qi = rsqrtf(sq * (1.f / 64.f) + 1e-6f);
    float ki = rsqrtf(sk * (1.f / 64.f) + 1e-6f);
    q1 *= qi * wq[lane];
    q2 *= qi * wq[lane + 32];
    k1 *= ki * wk[lane];
    k2 *= ki * wk[lane + 32];
    float freq = expf(-9.210340371976184f * (float)lane * (1.f / 32.f));
    float ang = (float)h * freq;
    float cs = cosf(ang), sn = sinf(ang);
    size_t o = (size_t)row * 256 + h * 64;
    qr[o + lane] = q1 * cs - q2 * sn;
    qr[o + lane + 32] = q1 * sn + q2 * cs;
    kr[o + lane] = k1 * cs - k2 * sn;
    kr[o + lane + 32] = k1 * sn + k2 * cs;
}

// ============================================================================
// Local attention (reg scores, shfl softmax/AV, 2 CTAs/SM).
// ============================================================================
__global__ __launch_bounds__(256, 2) void attn_k(
    const float* __restrict__ qr, const float* __restrict__ kr,
    const float* __restrict__ qkv,  // v = cols [512,768)
    const float* __restrict__ width, const float* __restrict__ sharp,
    float* __restrict__ out)
{
    extern __shared__ float sm[];
    float* ks = sm;
    float* vs = sm + 196 * KST;
    const int tile = blockIdx.x, h = blockIdx.y, b = blockIdx.z;
    const int ty0 = (tile >> 3) << 3;
    const int tx0 = (tile & 7) << 3;
    const int tid = threadIdx.x;

    for (int idx = tid; idx < 196 * 16; idx += 256) {
        int sp = idx >> 4, f = idx & 15;
        int yy = ty0 - 3 + sp / 14;
        int xx = tx0 - 3 + sp % 14;
        float4 kv = make_float4(0.f, 0.f, 0.f, 0.f);
        float4 vv = make_float4(0.f, 0.f, 0.f, 0.f);
        if (yy >= 0 && yy < GRIDW && xx >= 0 && xx < GRIDW) {
            int r = (b * GRIDW + yy) * GRIDW + xx;
            kv = *(const float4*)&kr[(size_t)r * 256 + h * 64 + f * 4];
            vv = *(const float4*)&qkv[(size_t)r * 768 + 512 + h * 64 + f * 4];
        }
        *(float4*)&ks[sp * KST + f * 4] = kv;
        *(float4*)&vs[sp * KST + f * 4] = vv;
    }
    __syncthreads();

    const int p = tid >> 2, sub = tid & 3;
    const int py = p >> 3, px = p & 7;
    const int row = (b * GRIDW + ty0 + py) * GRIDW + tx0 + px;

    const float wd = width[row * 4 + h];
    const float sh = sharp[row * 4 + h];

    float sr[13];
    {
        float q[64];
#pragma unroll
        for (int i = 0; i < 16; i++)
            *(float4*)&q[i * 4] = *(const float4*)&qr[(size_t)row * 256 + h * 64 + i * 4];

#pragma unroll
        for (int j = 0; j < 13; j++) {
            int w = sub + 4 * j;
            if (w < 49) {
                int wy = w / 7, wx = w % 7;
                const float* kp = &ks[((py + wy) * 14 + px + wx) * KST];
                float s0 = 0.f, s1 = 0.f, s2 = 0.f, s3 = 0.f;
#pragma unroll
                for (int i = 0; i < 16; i++) {
                    float4 kv = *(const float4*)&kp[i * 4];
                    s0 += q[i * 4 + 0] * kv.x;
                    s1 += q[i * 4 + 1] * kv.y;
                    s2 += q[i * 4 + 2] * kv.z;
                    s3 += q[i * 4 + 3] * kv.w;
                }
                float s = (s0 + s1) + (s2 + s3);
                float dy = (float)(wy - 3), dx = (float)(wx - 3);
                float rd = sqrtf(dy * dy + dx * dx);
                float soft = sigm((wd - rd) * sh);
                sr[j] = s * 0.125f - (1.f - soft) * 10000.f;
            } else {
                sr[j] = -1e30f;
            }
        }
    }

    float mx = sr[0];
#pragma unroll
    for (int j = 1; j < 13; j++) mx = fmaxf(mx, sr[j]);
    mx = fmaxf(mx, __shfl_xor_sync(0xffffffffu, mx, 1));
    mx = fmaxf(mx, __shfl_xor_sync(0xffffffffu, mx, 2));
    float sum = 0.f;
#pragma unroll
    for (int j = 0; j < 13; j++) {
        float e = expf(sr[j] - mx);
        sr[j] = e;
        sum += e;
    }
    sum += __shfl_xor_sync(0xffffffffu, sum, 1);
    sum += __shfl_xor_sync(0xffffffffu, sum, 2);
    float inv = 1.f / sum;

    float o[16];
#pragma unroll
    for (int i = 0; i < 16; i++) o[i] = 0.f;
#pragma unroll
    for (int w = 0; w < 49; w++) {
        const int j = w >> 2, owner = w & 3;
        float a = __shfl_sync(0xffffffffu, sr[j], owner, 4);
        const float* vp = &vs[((py + w / 7) * 14 + px + w % 7) * KST + sub * 16];
#pragma unroll
        for (int i = 0; i < 16; i++) o[i] += a * vp[i];
    }
#pragma unroll
    for (int i = 0; i < 4; i++) {
        float4 r = make_float4(o[i * 4] * inv, o[i * 4 + 1] * inv, o[i * 4 + 2] * inv, o[i * 4 + 3] * inv);
        *(float4*)&out[(size_t)row * 256 + h * 64 + sub * 16 + i * 4] = r;
    }
}

// ============================================================================
// inv-RMS per row of attention output.
// ============================================================================
__global__ __launch_bounds__(256) void irms_k(
    const float* __restrict__ attn, float* __restrict__ irms)
{
    int row = (blockIdx.x * 256 + threadIdx.x) >> 5;
    int lane = threadIdx.x & 31;
    if (row >= NROWS) return;
    const float* a = attn + (size_t)row * 256;
    float s = 0.f;
    for (int k = lane; k < 256; k += 32) {
        float v = a[k];
        s += v * v;
    }
#pragma unroll
    for (int off = 16; off; off >>= 1) s += __shfl_xor_sync(0xffffffffu, s, off);
    if (lane == 0) irms[row] = rsqrtf(s * (1.f / 256.f) + 1e-6f);
}

// ============================================================================
extern "C" void kernel_launch(void* const* d_in, const int* in_sizes, int n_in,
                              void* d_out, int out_size)
{
    const float* x      = (const float*)d_in[0];
    const float* W_qkv  = (const float*)d_in[1];
    const float* w_qn   = (const float*)d_in[2];
    const float* w_kn   = (const float*)d_in[3];
    const float* W_wp   = (const float*)d_in[4];
    const float* b_wp   = (const float*)d_in[5];
    const float* w_on   = (const float*)d_in[6];
    const float* W_out  = (const float*)d_in[7];
    const float* W_gate = (const float*)d_in[8];
    const float* b_gate = (const float*)d_in[9];
    float* out = (float*)d_out;

    float *qkv, *qr, *kr, *wd, *sh, *attn, *irms;
    __nv_bfloat16 *xh, *xl, *vh, *vl, *mh, *ml;
    __nv_bfloat16 *wqh, *wql, *wgh, *wgl, *woh, *wol;
    cudaGetSymbolAddress((void**)&qkv, g_qkv);
    cudaGetSymbolAddress((void**)&qr, g_qr);
    cudaGetSymbolAddress((void**)&kr, g_kr);
    cudaGetSymbolAddress((void**)&wd, g_width);
    cudaGetSymbolAddress((void**)&sh, g_sharp);
    cudaGetSymbolAddress((void**)&attn, g_attn);
    cudaGetSymbolAddress((void**)&irms, g_irms);
    cudaGetSymbolAddress((void**)&xh, g_xh);
    cudaGetSymbolAddress((void**)&xl, g_xl);
    cudaGetSymbolAddress((void**)&vh, g_vh);
    cudaGetSymbolAddress((void**)&vl, g_vl);
    cudaGetSymbolAddress((void**)&mh, g_mh);
    cudaGetSymbolAddress((void**)&ml, g_ml);
    cudaGetSymbolAddress((void**)&wqh, g_wqh);
    cudaGetSymbolAddress((void**)&wql, g_wql);
    cudaGetSymbolAddress((void**)&wgh, g_wgh);
    cudaGetSymbolAddress((void**)&wgl, g_wgl);
    cudaGetSymbolAddress((void**)&woh, g_woh);
    cudaGetSymbolAddress((void**)&wol, g_wol);

    const int SMEM_ATTN = (2 * 196 * KST) * 4;          // 106,624 B -> 2 CTAs/SM
    cudaFuncSetAttribute(attn_k, cudaFuncAttributeMaxDynamicSharedMemorySize, SMEM_ATTN);
    // staging: 4*128*ASTR*2 = 49,152 B ; epilogue: 8*32*CSTR*4 = 69,632 B
    const int SMEM_TC = 8 * 32 * CSTR * 4;              // 69,632 B
    cudaFuncSetAttribute(tc_gemm<0>, cudaFuncAttributeMaxDynamicSharedMemorySize, SMEM_TC);
    cudaFuncSetAttribute(tc_gemm<1>, cudaFuncAttributeMaxDynamicSharedMemorySize, SMEM_TC);
    cudaFuncSetAttribute(tc_gemm<2>, cudaFuncAttributeMaxDynamicSharedMemorySize, SMEM_TC);

    // 0) operand prep
    xsplit_k<<<NROWS, 256>>>(x, xh, xl);
    wsplit_k<<<768, 256>>>(W_qkv, 256, 768, wqh, wql);
    wsplit_k<<<256, 256>>>(W_gate, 256, 256, wgh, wgl);
    wsplit_k<<<256, 256>>>(W_out, 256, 256, woh, wol);

    // 1) qkv = silu(x @ W_qkv); also emits v bf16 split
    tc_gemm<0><<<dim3(6, 64), 256, SMEM_TC>>>(xh, xl, wqh, wql, qkv, 768,
                                              nullptr, nullptr, nullptr, nullptr, nullptr,
                                              vh, vl);
    // 2) width/sharpness
    wp_k<<<NROWS / 8, 256>>>(x, W_wp, b_wp, wd, sh);
    // 3) rmsnorm + rope on q,k
    normrope_k<<<NROWS * HEADS / 8, 256>>>(qkv, w_qn, w_kn, qr, kr);
    // 4) local attention
    attn_k<<<dim3(64, HEADS, 2), 256, SMEM_ATTN>>>(qr, kr, qkv, wd, sh, attn);
    // 5) inv-rms of attention output
    irms_k<<<NROWS / 8, 256>>>(attn, irms);
    // 6) gate GEMM + merge epilogue -> merged bf16 split
    tc_gemm<1><<<dim3(2, 64), 256, SMEM_TC>>>(vh, vl, wgh, wgl, nullptr, 256,
                                              b_gate, qkv, attn, irms, w_on,
                                              mh, ml);
    // 7) out = silu(merged @ W_out)
    tc_gemm<2><<<dim3(2, 64), 256, SMEM_TC>>>(mh, ml, woh, wol, out, 256,
                                              nullptr, nullptr, nullptr, nullptr, nullptr,
                                              nullptr, nullptr);
}